// round 5
// baseline (speedup 1.0000x reference)
#include <cuda_runtime.h>

#define N_NODES 100000
#define E_EDGES 1600000
#define HDIM    128
#define SCAN_B  1024
#define NSCANB  ((N_NODES + SCAN_B - 1) / SCAN_B)   // 98

// ---------------- scratch (static device globals; no runtime allocation) ----
__device__ int   g_is64;
__device__ int   g_degi[N_NODES];
__device__ float g_dinv[N_NODES];
__device__ int   g_src [E_EDGES];
__device__ int   g_dst [E_EDGES];
__device__ int   g_rows[N_NODES];        // per-block exclusive scan (pre-offset)
__device__ int   g_bsum[NSCANB];
__device__ int   g_boff[NSCANB];
__device__ int   g_rowstart[N_NODES + 1];
__device__ int   g_cursor[N_NODES];
__device__ int   g_csrc[E_EDGES];        // CSR: src node per in-edge, bucketed by dst
__device__ float g_cw  [E_EDGES];        // CSR: dinv[src]
__device__ __align__(16) float g_h [(size_t)N_NODES * HDIM];   // GEMM output
__device__ __align__(16) float g_a [(size_t)N_NODES * HDIM];   // aggregated output
__device__ float g_nsum[HDIM];
__device__ float g_cnt;

// ---------------- dtype detection -------------------------------------------
// JAX with default config silently downgrades jnp.int64 -> int32. Detect which
// layout the buffer actually has: valid int64 values must all be in [0, N).
__global__ void k_detect(const long long* __restrict__ ei) {
    int is64 = 1;
#pragma unroll
    for (int i = 0; i < 16; i++) {
        long long v = ei[i];
        if (v < 0 || v >= N_NODES) { is64 = 0; break; }
    }
    g_is64 = is64;
}

// ---------------- prep --------------------------------------------------------
__global__ void k_zero() {
    int i = blockIdx.x * blockDim.x + threadIdx.x;
    if (i < N_NODES) g_degi[i] = 0;
}

__global__ void k_prep(const void* __restrict__ eiv) {
    int e = blockIdx.x * blockDim.x + threadIdx.x;
    if (e >= E_EDGES) return;
    int s, d;
    if (g_is64) {
        const long long* p = (const long long*)eiv;
        s = (int)p[e];
        d = (int)p[E_EDGES + e];
    } else {
        const int* p = (const int*)eiv;
        s = p[e];
        d = p[E_EDGES + e];
    }
    // defensive: never issue a wild atomic
    if ((unsigned)s >= N_NODES || (unsigned)d >= N_NODES) { g_src[e] = 0; g_dst[e] = 0; return; }
    g_src[e] = s;
    g_dst[e] = d;
    atomicAdd(&g_degi[d], 1);
}

__global__ void k_dinv() {
    int i = blockIdx.x * blockDim.x + threadIdx.x;
    if (i < N_NODES) g_dinv[i] = rsqrtf((float)g_degi[i] + 1.f);
}

// ---------------- prefix sum (3 kernels) --------------------------------------
__global__ __launch_bounds__(SCAN_B) void k_scan1() {
    __shared__ int sh[SCAN_B];
    int tid = threadIdx.x;
    int i   = blockIdx.x * SCAN_B + tid;
    int v   = (i < N_NODES) ? g_degi[i] : 0;
    sh[tid] = v;
    __syncthreads();
#pragma unroll
    for (int off = 1; off < SCAN_B; off <<= 1) {
        int t = (tid >= off) ? sh[tid - off] : 0;
        __syncthreads();
        sh[tid] += t;
        __syncthreads();
    }
    if (i < N_NODES) g_rows[i] = sh[tid] - v;          // exclusive, pre-offset
    if (tid == SCAN_B - 1) g_bsum[blockIdx.x] = sh[tid];
}

__global__ void k_scan2() {      // single block, 128 threads >= NSCANB(98)
    __shared__ int sh[128];
    int tid = threadIdx.x;
    int v   = (tid < NSCANB) ? g_bsum[tid] : 0;
    sh[tid] = v;
    __syncthreads();
#pragma unroll
    for (int off = 1; off < 128; off <<= 1) {
        int t = (tid >= off) ? sh[tid - off] : 0;
        __syncthreads();
        sh[tid] += t;
        __syncthreads();
    }
    if (tid < NSCANB) g_boff[tid] = sh[tid] - v;       // exclusive
}

__global__ __launch_bounds__(SCAN_B) void k_scan3() {
    int i = blockIdx.x * SCAN_B + threadIdx.x;
    if (i < N_NODES) {
        int rs = g_rows[i] + g_boff[blockIdx.x];
        g_rowstart[i] = rs;
        g_cursor[i]   = rs;
    }
    if (i == 0) g_rowstart[N_NODES] = E_EDGES;
}

// ---------------- CSR fill -----------------------------------------------------
__global__ void k_fill() {
    int e = blockIdx.x * blockDim.x + threadIdx.x;
    if (e >= E_EDGES) return;
    int s = g_src[e];
    int d = g_dst[e];
    int pos = atomicAdd(&g_cursor[d], 1);
    g_csrc[pos] = s;
    g_cw[pos]   = g_dinv[s];
}

// ---------------- GEMM: O[N,128] = (relu?)(A[N,128]) @ W[128,128] ------------
template <bool RELU_IN>
__global__ __launch_bounds__(256) void k_gemm(const float* __restrict__ A,
                                              const float* __restrict__ W,
                                              float* __restrict__ O) {
    __shared__ float As[16][64];    // K-major
    __shared__ float Bs[16][128];

    const int t  = threadIdx.x;
    const int tx = t & 31;
    const int ty = t >> 5;
    const int rowBase = blockIdx.x * 64;

    float acc[8][4];
#pragma unroll
    for (int i = 0; i < 8; i++)
#pragma unroll
        for (int j = 0; j < 4; j++) acc[i][j] = 0.f;

    const int aRow = t >> 2;
    const int aK   = (t & 3) * 4;

#pragma unroll
    for (int k0 = 0; k0 < 128; k0 += 16) {
        float4 av = make_float4(0.f, 0.f, 0.f, 0.f);
        int gr = rowBase + aRow;
        if (gr < N_NODES)
            av = *(const float4*)(A + (size_t)gr * HDIM + k0 + aK);
        if (RELU_IN) {
            av.x = fmaxf(av.x, 0.f); av.y = fmaxf(av.y, 0.f);
            av.z = fmaxf(av.z, 0.f); av.w = fmaxf(av.w, 0.f);
        }
        As[aK + 0][aRow] = av.x;
        As[aK + 1][aRow] = av.y;
        As[aK + 2][aRow] = av.z;
        As[aK + 3][aRow] = av.w;

#pragma unroll
        for (int f = 0; f < 2; f++) {
            int idx = t + f * 256;
            int kr  = idx >> 5;
            int cg  = idx & 31;
            float4 bv = *(const float4*)(W + (size_t)(k0 + kr) * HDIM + cg * 4);
            *(float4*)&Bs[kr][cg * 4] = bv;
        }
        __syncthreads();

#pragma unroll
        for (int kk = 0; kk < 16; kk++) {
            float4 a0 = *(const float4*)&As[kk][ty * 8];
            float4 a1 = *(const float4*)&As[kk][ty * 8 + 4];
            float4 b  = *(const float4*)&Bs[kk][tx * 4];
            float ar[8] = {a0.x, a0.y, a0.z, a0.w, a1.x, a1.y, a1.z, a1.w};
            float br[4] = {b.x, b.y, b.z, b.w};
#pragma unroll
            for (int i = 0; i < 8; i++)
#pragma unroll
                for (int j = 0; j < 4; j++)
                    acc[i][j] = fmaf(ar[i], br[j], acc[i][j]);
        }
        __syncthreads();
    }

#pragma unroll
    for (int i = 0; i < 8; i++) {
        int row = rowBase + ty * 8 + i;
        if (row < N_NODES) {
            float4 v = make_float4(acc[i][0], acc[i][1], acc[i][2], acc[i][3]);
            *(float4*)(O + (size_t)row * HDIM + tx * 4) = v;
        }
    }
}

// ---------------- gather-side aggregation --------------------------------------
// one warp per node; a[d] = (Σ_e h[src_e]*dinv[src_e] + h[d]*dinv_d) * dinv_d + b
__global__ __launch_bounds__(256) void k_agg(const float* __restrict__ bias) {
    int w    = (blockIdx.x * blockDim.x + threadIdx.x) >> 5;
    int lane = threadIdx.x & 31;
    if (w >= N_NODES) return;

    int beg = g_rowstart[w];
    int end = g_rowstart[w + 1];

    float4 acc = make_float4(0.f, 0.f, 0.f, 0.f);
    int e = beg;
    for (; e + 1 < end; e += 2) {
        int   s0 = g_csrc[e];     int   s1 = g_csrc[e + 1];
        float w0 = g_cw[e];       float w1 = g_cw[e + 1];
        float4 v0 = ((const float4*)(g_h + (size_t)s0 * HDIM))[lane];
        float4 v1 = ((const float4*)(g_h + (size_t)s1 * HDIM))[lane];
        acc.x = fmaf(v0.x, w0, acc.x); acc.y = fmaf(v0.y, w0, acc.y);
        acc.z = fmaf(v0.z, w0, acc.z); acc.w = fmaf(v0.w, w0, acc.w);
        acc.x = fmaf(v1.x, w1, acc.x); acc.y = fmaf(v1.y, w1, acc.y);
        acc.z = fmaf(v1.z, w1, acc.z); acc.w = fmaf(v1.w, w1, acc.w);
    }
    if (e < end) {
        int   s0 = g_csrc[e];
        float w0 = g_cw[e];
        float4 v0 = ((const float4*)(g_h + (size_t)s0 * HDIM))[lane];
        acc.x = fmaf(v0.x, w0, acc.x); acc.y = fmaf(v0.y, w0, acc.y);
        acc.z = fmaf(v0.z, w0, acc.z); acc.w = fmaf(v0.w, w0, acc.w);
    }

    float  di = g_dinv[w];
    float4 hv = ((const float4*)(g_h + (size_t)w * HDIM))[lane];
    float4 b4 = ((const float4*)bias)[lane];
    float4 o;
    o.x = fmaf(fmaf(hv.x, di, acc.x), di, b4.x);
    o.y = fmaf(fmaf(hv.y, di, acc.y), di, b4.y);
    o.z = fmaf(fmaf(hv.z, di, acc.z), di, b4.z);
    o.w = fmaf(fmaf(hv.w, di, acc.w), di, b4.w);
    ((float4*)(g_a + (size_t)w * HDIM))[lane] = o;
}

// ---------------- readout -------------------------------------------------------
__global__ void k_neigh() {          // 1 block, 128 threads; CSR row of node 0
    int t   = threadIdx.x;
    int beg = g_rowstart[0];
    int end = g_rowstart[1];
    float sum = 0.f;
    for (int e = beg; e < end; e++) {
        int s = g_csrc[e];
        sum += fmaxf(g_a[(size_t)s * HDIM + t], 0.f);
    }
    g_nsum[t] = sum;
    if (t == 0) g_cnt = (float)(end - beg);
}

__global__ void k_final(const float* __restrict__ fcw,
                        const float* __restrict__ fcb,
                        float* __restrict__ out) {
    int t = threadIdx.x;   // 128 threads
    float cnt = fmaxf(g_cnt, 1.f);
    float v = fmaxf(g_a[t], 0.f) * fcw[t] + (g_nsum[t] / cnt) * fcw[HDIM + t];
#pragma unroll
    for (int off = 16; off > 0; off >>= 1)
        v += __shfl_xor_sync(0xFFFFFFFFu, v, off);
    __shared__ float red[4];
    if ((t & 31) == 0) red[t >> 5] = v;
    __syncthreads();
    if (t == 0) out[0] = red[0] + red[1] + red[2] + red[3] + fcb[0];
}

// ---------------- launcher --------------------------------------------------------
extern "C" void kernel_launch(void* const* d_in, const int* in_sizes, int n_in,
                              void* d_out, int out_size) {
    // Identify inputs by element count (robust to metadata ordering).
    const float* x   = nullptr;
    const void*  ei  = nullptr;
    const float* w1  = nullptr;
    const float* b1  = nullptr;
    const float* w2  = nullptr;
    const float* b2  = nullptr;
    const float* fcw = nullptr;
    const float* fcb = nullptr;
    for (int i = 0; i < n_in; i++) {
        switch (in_sizes[i]) {
            case 12800000: x   = (const float*)d_in[i];     break;
            case 3200000:  ei  = d_in[i];                   break;
            case 100000:   /* concentration, unused */      break;
            case 16384:    if (!w1) w1 = (const float*)d_in[i];
                           else      w2 = (const float*)d_in[i]; break;
            case 128:      if (!b1) b1 = (const float*)d_in[i];
                           else      b2 = (const float*)d_in[i]; break;
            case 256:      fcw = (const float*)d_in[i];     break;
            case 1:        fcb = (const float*)d_in[i];     break;
            default: break;
        }
    }
    float* out = (float*)d_out;

    // Device addresses of scratch symbols (host &g_h would be the CPU shadow)
    float *p_h = nullptr, *p_a = nullptr;
    cudaGetSymbolAddress((void**)&p_h, g_h);
    cudaGetSymbolAddress((void**)&p_a, g_a);

    const int TB = 256;
    const int gN   = (N_NODES + TB - 1) / TB;
    const int gE   = (E_EDGES + TB - 1) / TB;
    const int gRow = (N_NODES + 63) / 64;
    const int gAgg = (N_NODES * 32 + TB - 1) / TB;   // one warp per node

    // CSR build
    k_detect<<<1, 1>>>((const long long*)ei);
    k_zero <<<gN, TB>>>();
    k_prep <<<gE, TB>>>(ei);
    k_dinv <<<gN, TB>>>();
    k_scan1<<<NSCANB, SCAN_B>>>();
    k_scan2<<<1, 128>>>();
    k_scan3<<<NSCANB, SCAN_B>>>();
    k_fill <<<gE, TB>>>();

    // layer 1
    k_gemm<false><<<gRow, TB>>>(x, w1, p_h);
    k_agg<<<gAgg, TB>>>(b1);

    // layer 2 (relu fused into GEMM A-load)
    k_gemm<true><<<gRow, TB>>>(p_a, w2, p_h);
    k_agg<<<gAgg, TB>>>(b2);

    // readout
    k_neigh<<<1, 128>>>();
    k_final<<<1, 128>>>(fcw, fcb, out);
}

// round 7
// speedup vs baseline: 1.1805x; 1.1805x over previous
#include <cuda_runtime.h>
#include <cuda_bf16.h>
#include <cstdint>

#define N_NODES 100000
#define E_EDGES 1600000
#define HDIM    128
#define SCAN_B  1024
#define NSCANB  ((N_NODES + SCAN_B - 1) / SCAN_B)   // 98

// ---------------- scratch (static device globals; no runtime allocation) ----
__device__ int   g_is64;
__device__ int   g_degi[N_NODES];
__device__ float g_dinv[N_NODES];
__device__ int   g_src [E_EDGES];
__device__ int   g_dst [E_EDGES];
__device__ int   g_rows[N_NODES];
__device__ int   g_bsum[NSCANB];
__device__ int   g_boff[NSCANB];
__device__ int   g_rowstart[N_NODES + 1];
__device__ int   g_cursor[N_NODES];
__device__ int   g_csrc[E_EDGES];
__device__ float g_cw  [E_EDGES];
__device__ __align__(16) float g_h [(size_t)N_NODES * HDIM];
__device__ __align__(16) float g_a [(size_t)N_NODES * HDIM];
// pre-tiled bf16 weight images (exact SMEM 8x8-block layout, 32KB each)
__device__ __align__(16) __nv_bfloat16 g_w1hi[16384];
__device__ __align__(16) __nv_bfloat16 g_w1lo[16384];
__device__ __align__(16) __nv_bfloat16 g_w2hi[16384];
__device__ __align__(16) __nv_bfloat16 g_w2lo[16384];

// ---------------- PTX helpers -------------------------------------------------
__device__ __forceinline__ uint32_t smem_u32(const void* p) {
    uint32_t a;
    asm("{ .reg .u64 t; cvta.to.shared.u64 t, %1; cvt.u32.u64 %0, t; }" : "=r"(a) : "l"(p));
    return a;
}
__device__ __forceinline__ void ldsm4(uint32_t* r, uint32_t addr) {
    asm volatile("ldmatrix.sync.aligned.m8n8.x4.shared.b16 {%0,%1,%2,%3}, [%4];"
                 : "=r"(r[0]), "=r"(r[1]), "=r"(r[2]), "=r"(r[3]) : "r"(addr));
}
__device__ __forceinline__ void mma_bf16(float* c, const uint32_t* a, uint32_t b0, uint32_t b1) {
    asm volatile("mma.sync.aligned.m16n8k16.row.col.f32.bf16.bf16.f32 "
                 "{%0,%1,%2,%3}, {%4,%5,%6,%7}, {%8,%9}, {%0,%1,%2,%3};"
                 : "+f"(c[0]), "+f"(c[1]), "+f"(c[2]), "+f"(c[3])
                 : "r"(a[0]), "r"(a[1]), "r"(a[2]), "r"(a[3]), "r"(b0), "r"(b1));
}

// 8x8-block tile layout (r = m or n index 0..127, k = 0..127):
// block(rblk, k16, khalf) linear = ((rblk*8 + k16)*2 + khalf), 128B per block,
// within block: row (r&7) at +16*(r&7), element (k&7) at +2*(k&7).
__device__ __forceinline__ uint32_t tile_addr(int r, int k) {
    uint32_t blk = (uint32_t)(((r >> 3) * 8 + (k >> 4)) * 2 + ((k >> 3) & 1));
    return blk * 128 + (uint32_t)((r & 7) * 16 + (k & 7) * 2);
}

// ---------------- prep / CSR build --------------------------------------------
__global__ void k_init(const long long* __restrict__ ei) {
    int i = blockIdx.x * blockDim.x + threadIdx.x;
    if (i < N_NODES) g_degi[i] = 0;
    if (blockIdx.x == 0 && threadIdx.x == 0) {
        int is64 = 1;
#pragma unroll
        for (int j = 0; j < 16; j++) {
            long long v = ei[j];
            if (v < 0 || v >= N_NODES) { is64 = 0; break; }
        }
        g_is64 = is64;
    }
}

__global__ void k_prep(const void* __restrict__ eiv) {
    int e = blockIdx.x * blockDim.x + threadIdx.x;
    if (e >= E_EDGES) return;
    int s, d;
    if (g_is64) {
        const long long* p = (const long long*)eiv;
        s = (int)p[e];
        d = (int)p[E_EDGES + e];
    } else {
        const int* p = (const int*)eiv;
        s = p[e];
        d = p[E_EDGES + e];
    }
    if ((unsigned)s >= N_NODES || (unsigned)d >= N_NODES) { g_src[e] = 0; g_dst[e] = 0; return; }
    g_src[e] = s;
    g_dst[e] = d;
    atomicAdd(&g_degi[d], 1);
}

__global__ __launch_bounds__(SCAN_B) void k_scan1() {
    __shared__ int sh[SCAN_B];
    int tid = threadIdx.x;
    int i   = blockIdx.x * SCAN_B + tid;
    int v   = (i < N_NODES) ? g_degi[i] : 0;
    if (i < N_NODES) g_dinv[i] = rsqrtf((float)v + 1.f);
    sh[tid] = v;
    __syncthreads();
#pragma unroll
    for (int off = 1; off < SCAN_B; off <<= 1) {
        int t = (tid >= off) ? sh[tid - off] : 0;
        __syncthreads();
        sh[tid] += t;
        __syncthreads();
    }
    if (i < N_NODES) g_rows[i] = sh[tid] - v;
    if (tid == SCAN_B - 1) g_bsum[blockIdx.x] = sh[tid];
}

__global__ void k_scan2() {
    __shared__ int sh[128];
    int tid = threadIdx.x;
    int v   = (tid < NSCANB) ? g_bsum[tid] : 0;
    sh[tid] = v;
    __syncthreads();
#pragma unroll
    for (int off = 1; off < 128; off <<= 1) {
        int t = (tid >= off) ? sh[tid - off] : 0;
        __syncthreads();
        sh[tid] += t;
        __syncthreads();
    }
    if (tid < NSCANB) g_boff[tid] = sh[tid] - v;
}

__global__ __launch_bounds__(SCAN_B) void k_scan3() {
    int i = blockIdx.x * SCAN_B + threadIdx.x;
    if (i < N_NODES) {
        int rs = g_rows[i] + g_boff[blockIdx.x];
        g_rowstart[i] = rs;
        g_cursor[i]   = rs;
    }
    if (i == 0) g_rowstart[N_NODES] = E_EDGES;
}

__global__ void k_fill() {
    int e = blockIdx.x * blockDim.x + threadIdx.x;
    if (e >= E_EDGES) return;
    int s = g_src[e];
    int d = g_dst[e];
    int pos = atomicAdd(&g_cursor[d], 1);
    g_csrc[pos] = s;
    g_cw[pos]   = g_dinv[s];
}

// ---------------- weight pre-conversion (bf16 hi/lo, pre-tiled images) --------
// B[n][k] = w[k][n]
__global__ void k_wconv(const float* __restrict__ w1, const float* __restrict__ w2) {
    int i = blockIdx.x * blockDim.x + threadIdx.x;    // 0..32767
    const float* w = (i < 16384) ? w1 : w2;
    __nv_bfloat16* hi = (i < 16384) ? g_w1hi : g_w2hi;
    __nv_bfloat16* lo = (i < 16384) ? g_w1lo : g_w2lo;
    int j = i & 16383;
    int k = j >> 7, n = j & 127;
    float v = w[j];
    __nv_bfloat16 h = __float2bfloat16(v);
    __nv_bfloat16 l = __float2bfloat16(v - __bfloat162float(h));
    uint32_t a = tile_addr(n, k);
    *(__nv_bfloat16*)((char*)hi + a) = h;
    *(__nv_bfloat16*)((char*)lo + a) = l;
}

// ---------------- HMMA GEMM: O[N,128] = (relu?)A[N,128] @ W[128,128] ----------
// 1 CTA = 128 rows, 256 threads = 8 warps, warp w -> rows w*16..w*16+15 (all cols).
// bf16 hi/lo split, 3 mma products, fp32 accumulate.
#define SM_AHI  0
#define SM_ALO  32768
#define SM_BHI  65536
#define SM_BLO  98304
#define SM_TOT  131072

template <bool RELU_IN>
__global__ __launch_bounds__(256)
void k_gemm_mma(const float* __restrict__ A,
                const __nv_bfloat16* __restrict__ Whi,
                const __nv_bfloat16* __restrict__ Wlo,
                float* __restrict__ O) {
    extern __shared__ char smem[];
    const uint32_t sbase = smem_u32(smem);
    const int tid  = threadIdx.x;
    const int wid  = tid >> 5;
    const int lane = tid & 31;
    const int rowBase = blockIdx.x * 128;

    // copy pre-tiled W images (2 x 32KB)
#pragma unroll
    for (int i = 0; i < 8; i++) {
        int idx = i * 256 + tid;                       // 0..2047 uint4
        ((uint4*)(smem + SM_BHI))[idx] = ((const uint4*)Whi)[idx];
        ((uint4*)(smem + SM_BLO))[idx] = ((const uint4*)Wlo)[idx];
    }

    // load + split-convert A tile (128 rows x 128 fp32 -> bf16 hi/lo tiles)
#pragma unroll
    for (int i = 0; i < 16; i++) {
        int f4  = i * 256 + tid;                       // 0..4095 float4
        int row = f4 >> 5;
        int c4  = f4 & 31;
        int gr  = rowBase + row;
        float4 v = make_float4(0.f, 0.f, 0.f, 0.f);
        if (gr < N_NODES) v = *(const float4*)(A + (size_t)gr * HDIM + c4 * 4);
        if (RELU_IN) {
            v.x = fmaxf(v.x, 0.f); v.y = fmaxf(v.y, 0.f);
            v.z = fmaxf(v.z, 0.f); v.w = fmaxf(v.w, 0.f);
        }
        __nv_bfloat162 h01 = __floats2bfloat162_rn(v.x, v.y);
        __nv_bfloat162 h23 = __floats2bfloat162_rn(v.z, v.w);
        float2 f01 = __bfloat1622float2(h01);
        float2 f23 = __bfloat1622float2(h23);
        __nv_bfloat162 l01 = __floats2bfloat162_rn(v.x - f01.x, v.y - f01.y);
        __nv_bfloat162 l23 = __floats2bfloat162_rn(v.z - f23.x, v.w - f23.y);
        uint32_t addr = tile_addr(row, c4 * 4);        // 8B within one block row
        uint2 uh, ul;
        uh.x = *(uint32_t*)&h01; uh.y = *(uint32_t*)&h23;
        ul.x = *(uint32_t*)&l01; ul.y = *(uint32_t*)&l23;
        *(uint2*)(smem + SM_AHI + addr) = uh;
        *(uint2*)(smem + SM_ALO + addr) = ul;
    }
    __syncthreads();

    float acc[16][4];
#pragma unroll
    for (int i = 0; i < 16; i++)
#pragma unroll
        for (int j = 0; j < 4; j++) acc[i][j] = 0.f;

    const int mb0 = wid * 2;            // warp's two 8-row m-blocks
    // ldmatrix lane addressing
    const int ablk = lane >> 3;         // 0..3
    const int arow = lane & 7;
    const int a_mblk  = mb0 + (ablk & 1);
    const int a_khalf = ablk >> 1;
    const int b_noff  = ablk >> 1;      // 0,0,1,1  (nblk offset)
    const int b_khalf = ablk & 1;       // 0,1,0,1

#pragma unroll
    for (int k16 = 0; k16 < 8; k16++) {
        uint32_t a_addr = sbase + (uint32_t)((((a_mblk * 8 + k16) * 2 + a_khalf) * 128) + arow * 16);
        uint32_t ahi[4], alo[4];
        ldsm4(ahi, a_addr + SM_AHI);
        ldsm4(alo, a_addr + SM_ALO);

#pragma unroll
        for (int nb2 = 0; nb2 < 8; nb2++) {
            int nblk = nb2 * 2 + b_noff;
            uint32_t b_addr = sbase + (uint32_t)((((nblk * 8 + k16) * 2 + b_khalf) * 128) + arow * 16);
            uint32_t bh[4], bl[4];
            ldsm4(bh, b_addr + SM_BHI);
            ldsm4(bl, b_addr + SM_BLO);
            // nblk pair: frag for nb2*2 = {r0,r1}, nb2*2+1 = {r2,r3}
            mma_bf16(acc[nb2 * 2],     ahi, bh[0], bh[1]);
            mma_bf16(acc[nb2 * 2],     ahi, bl[0], bl[1]);
            mma_bf16(acc[nb2 * 2],     alo, bh[0], bh[1]);
            mma_bf16(acc[nb2 * 2 + 1], ahi, bh[2], bh[3]);
            mma_bf16(acc[nb2 * 2 + 1], ahi, bl[2], bl[3]);
            mma_bf16(acc[nb2 * 2 + 1], alo, bh[2], bh[3]);
        }
    }

    // epilogue: c0,c1 = (m = g, n = q*2, q*2+1), c2,c3 = (m = g+8)
    int g = lane >> 2;
    int q = lane & 3;
    int r0 = rowBase + wid * 16 + g;
    int r1 = r0 + 8;
#pragma unroll
    for (int nb = 0; nb < 16; nb++) {
        int col = nb * 8 + q * 2;
        if (r0 < N_NODES) *(float2*)(O + (size_t)r0 * HDIM + col) = make_float2(acc[nb][0], acc[nb][1]);
        if (r1 < N_NODES) *(float2*)(O + (size_t)r1 * HDIM + col) = make_float2(acc[nb][2], acc[nb][3]);
    }
}

// ---------------- gather-side aggregation -------------------------------------
__global__ __launch_bounds__(256) void k_agg(const float* __restrict__ bias) {
    int w    = (blockIdx.x * blockDim.x + threadIdx.x) >> 5;
    int lane = threadIdx.x & 31;
    if (w >= N_NODES) return;

    int beg = g_rowstart[w];
    int end = g_rowstart[w + 1];

    float4 acc = make_float4(0.f, 0.f, 0.f, 0.f);
    int e = beg;
    for (; e + 1 < end; e += 2) {
        int   s0 = g_csrc[e];     int   s1 = g_csrc[e + 1];
        float w0 = g_cw[e];       float w1 = g_cw[e + 1];
        float4 v0 = ((const float4*)(g_h + (size_t)s0 * HDIM))[lane];
        float4 v1 = ((const float4*)(g_h + (size_t)s1 * HDIM))[lane];
        acc.x = fmaf(v0.x, w0, acc.x); acc.y = fmaf(v0.y, w0, acc.y);
        acc.z = fmaf(v0.z, w0, acc.z); acc.w = fmaf(v0.w, w0, acc.w);
        acc.x = fmaf(v1.x, w1, acc.x); acc.y = fmaf(v1.y, w1, acc.y);
        acc.z = fmaf(v1.z, w1, acc.z); acc.w = fmaf(v1.w, w1, acc.w);
    }
    if (e < end) {
        int   s0 = g_csrc[e];
        float w0 = g_cw[e];
        float4 v0 = ((const float4*)(g_h + (size_t)s0 * HDIM))[lane];
        acc.x = fmaf(v0.x, w0, acc.x); acc.y = fmaf(v0.y, w0, acc.y);
        acc.z = fmaf(v0.z, w0, acc.z); acc.w = fmaf(v0.w, w0, acc.w);
    }

    float  di = g_dinv[w];
    float4 hv = ((const float4*)(g_h + (size_t)w * HDIM))[lane];
    float4 b4 = ((const float4*)bias)[lane];
    float4 o;
    o.x = fmaf(fmaf(hv.x, di, acc.x), di, b4.x);
    o.y = fmaf(fmaf(hv.y, di, acc.y), di, b4.y);
    o.z = fmaf(fmaf(hv.z, di, acc.z), di, b4.z);
    o.w = fmaf(fmaf(hv.w, di, acc.w), di, b4.w);
    ((float4*)(g_a + (size_t)w * HDIM))[lane] = o;
}

// ---------------- readout ------------------------------------------------------
__global__ void k_readout(const float* __restrict__ fcw,
                          const float* __restrict__ fcb,
                          float* __restrict__ out) {
    int t   = threadIdx.x;                 // 128 threads
    int beg = g_rowstart[0];
    int end = g_rowstart[1];
    float sum = 0.f;
    for (int e = beg; e < end; e++) {
        int s = g_csrc[e];
        sum += fmaxf(g_a[(size_t)s * HDIM + t], 0.f);
    }
    float cnt = fmaxf((float)(end - beg), 1.f);
    float v = fmaxf(g_a[t], 0.f) * fcw[t] + (sum / cnt) * fcw[HDIM + t];
#pragma unroll
    for (int off = 16; off > 0; off >>= 1)
        v += __shfl_xor_sync(0xFFFFFFFFu, v, off);
    __shared__ float red[4];
    if ((t & 31) == 0) red[t >> 5] = v;
    __syncthreads();
    if (t == 0) out[0] = red[0] + red[1] + red[2] + red[3] + fcb[0];
}

// ---------------- launcher -------------------------------------------------------
extern "C" void kernel_launch(void* const* d_in, const int* in_sizes, int n_in,
                              void* d_out, int out_size) {
    const float* x   = nullptr;
    const void*  ei  = nullptr;
    const float* w1  = nullptr;
    const float* b1  = nullptr;
    const float* w2  = nullptr;
    const float* b2  = nullptr;
    const float* fcw = nullptr;
    const float* fcb = nullptr;
    for (int i = 0; i < n_in; i++) {
        switch (in_sizes[i]) {
            case 12800000: x   = (const float*)d_in[i];     break;
            case 3200000:  ei  = d_in[i];                   break;
            case 100000:   break;
            case 16384:    if (!w1) w1 = (const float*)d_in[i];
                           else      w2 = (const float*)d_in[i]; break;
            case 128:      if (!b1) b1 = (const float*)d_in[i];
                           else      b2 = (const float*)d_in[i]; break;
            case 256:      fcw = (const float*)d_in[i];     break;
            case 1:        fcb = (const float*)d_in[i];     break;
            default: break;
        }
    }
    float* out = (float*)d_out;

    float *p_h = nullptr, *p_a = nullptr;
    __nv_bfloat16 *p_w1hi = nullptr, *p_w1lo = nullptr, *p_w2hi = nullptr, *p_w2lo = nullptr;
    cudaGetSymbolAddress((void**)&p_h, g_h);
    cudaGetSymbolAddress((void**)&p_a, g_a);
    cudaGetSymbolAddress((void**)&p_w1hi, g_w1hi);
    cudaGetSymbolAddress((void**)&p_w1lo, g_w1lo);
    cudaGetSymbolAddress((void**)&p_w2hi, g_w2hi);
    cudaGetSymbolAddress((void**)&p_w2lo, g_w2lo);

    cudaFuncSetAttribute(k_gemm_mma<false>, cudaFuncAttributeMaxDynamicSharedMemorySize, SM_TOT);
    cudaFuncSetAttribute(k_gemm_mma<true>,  cudaFuncAttributeMaxDynamicSharedMemorySize, SM_TOT);

    const int TB = 256;
    const int gN    = (N_NODES + TB - 1) / TB;
    const int gE    = (E_EDGES + TB - 1) / TB;
    const int gTile = (N_NODES + 127) / 128;          // 782
    const int gAgg  = (N_NODES * 32 + TB - 1) / TB;

    // CSR build + weight conversion
    k_init <<<gN, TB>>>((const long long*)ei);
    k_prep <<<gE, TB>>>(ei);
    k_scan1<<<NSCANB, SCAN_B>>>();
    k_scan2<<<1, 128>>>();
    k_scan3<<<NSCANB, SCAN_B>>>();
    k_fill <<<gE, TB>>>();
    k_wconv<<<128, TB>>>(w1, w2);

    // layer 1
    k_gemm_mma<false><<<gTile, TB, SM_TOT>>>(x, p_w1hi, p_w1lo, p_h);
    k_agg<<<gAgg, TB>>>(b1);

    // layer 2 (relu fused into A conversion)
    k_gemm_mma<true><<<gTile, TB, SM_TOT>>>(p_a, p_w2hi, p_w2lo, p_h);
    k_agg<<<gAgg, TB>>>(b2);

    // readout
    k_readout<<<1, 128>>>(fcw, fcb, out);
}

// round 8
// speedup vs baseline: 1.3258x; 1.1231x over previous
#include <cuda_runtime.h>
#include <cuda_bf16.h>
#include <cuda_fp16.h>
#include <cstdint>

#define N_NODES 100000
#define E_EDGES 1600000
#define HDIM    128
#define SCAN_B  1024
#define NSCANB  ((N_NODES + SCAN_B - 1) / SCAN_B)   // 98

// ---------------- scratch (static device globals; no runtime allocation) ----
__device__ int   g_is64;
__device__ int   g_degi[N_NODES];
__device__ float g_dinv[N_NODES];
__device__ int   g_src [E_EDGES];
__device__ int   g_dst [E_EDGES];
__device__ int   g_rows[N_NODES];
__device__ int   g_bsum[NSCANB];
__device__ int   g_rowstart[N_NODES + 1];
__device__ int   g_cursor[N_NODES];
__device__ int   g_csrc[E_EDGES];
__device__ float g_cw  [E_EDGES];
__device__ __align__(16) __half g_h16[(size_t)N_NODES * HDIM];  // GEMM out (fp16)
__device__ __align__(16) float  g_a  [(size_t)N_NODES * HDIM];  // agg out (fp32)
// pre-tiled bf16 weight images (exact SMEM 8x8-block layout, 32KB each)
__device__ __align__(16) __nv_bfloat16 g_w1hi[16384];
__device__ __align__(16) __nv_bfloat16 g_w1lo[16384];
__device__ __align__(16) __nv_bfloat16 g_w2hi[16384];
__device__ __align__(16) __nv_bfloat16 g_w2lo[16384];

// ---------------- PTX helpers -------------------------------------------------
__device__ __forceinline__ uint32_t smem_u32(const void* p) {
    uint32_t a;
    asm("{ .reg .u64 t; cvta.to.shared.u64 t, %1; cvt.u32.u64 %0, t; }" : "=r"(a) : "l"(p));
    return a;
}
__device__ __forceinline__ void ldsm4(uint32_t* r, uint32_t addr) {
    asm volatile("ldmatrix.sync.aligned.m8n8.x4.shared.b16 {%0,%1,%2,%3}, [%4];"
                 : "=r"(r[0]), "=r"(r[1]), "=r"(r[2]), "=r"(r[3]) : "r"(addr));
}
__device__ __forceinline__ void mma_bf16(float* c, const uint32_t* a, uint32_t b0, uint32_t b1) {
    asm volatile("mma.sync.aligned.m16n8k16.row.col.f32.bf16.bf16.f32 "
                 "{%0,%1,%2,%3}, {%4,%5,%6,%7}, {%8,%9}, {%0,%1,%2,%3};"
                 : "+f"(c[0]), "+f"(c[1]), "+f"(c[2]), "+f"(c[3])
                 : "r"(a[0]), "r"(a[1]), "r"(a[2]), "r"(a[3]), "r"(b0), "r"(b1));
}

// 8x8-block tile layout (r = m or n index 0..127, k = 0..127)
__device__ __forceinline__ uint32_t tile_addr(int r, int k) {
    uint32_t blk = (uint32_t)(((r >> 3) * 8 + (k >> 4)) * 2 + ((k >> 3) & 1));
    return blk * 128 + (uint32_t)((r & 7) * 16 + (k & 7) * 2);
}

// ---------------- prep / CSR build --------------------------------------------
__global__ void k_init(const long long* __restrict__ ei) {
    int i = blockIdx.x * blockDim.x + threadIdx.x;
    if (i < N_NODES) g_degi[i] = 0;
    if (blockIdx.x == 0 && threadIdx.x == 0) {
        int is64 = 1;
#pragma unroll
        for (int j = 0; j < 16; j++) {
            long long v = ei[j];
            if (v < 0 || v >= N_NODES) { is64 = 0; break; }
        }
        g_is64 = is64;
    }
}

__global__ void k_prep(const void* __restrict__ eiv) {
    int e = blockIdx.x * blockDim.x + threadIdx.x;
    if (e >= E_EDGES) return;
    int s, d;
    if (g_is64) {
        const long long* p = (const long long*)eiv;
        s = (int)p[e];
        d = (int)p[E_EDGES + e];
    } else {
        const int* p = (const int*)eiv;
        s = p[e];
        d = p[E_EDGES + e];
    }
    if ((unsigned)s >= N_NODES || (unsigned)d >= N_NODES) { g_src[e] = 0; g_dst[e] = 0; return; }
    g_src[e] = s;
    g_dst[e] = d;
    atomicAdd(&g_degi[d], 1);
}

// scan phase 1 + weight conversion (merged grids; blocks >= NSCANB do wconv)
__global__ __launch_bounds__(SCAN_B) void k_scan1(const float* __restrict__ w1,
                                                  const float* __restrict__ w2) {
    if (blockIdx.x >= NSCANB) {
        int i = (int)(blockIdx.x - NSCANB) * SCAN_B + threadIdx.x;   // 0..32767
        if (i < 32768) {
            const float* w = (i < 16384) ? w1 : w2;
            __nv_bfloat16* hi = (i < 16384) ? g_w1hi : g_w2hi;
            __nv_bfloat16* lo = (i < 16384) ? g_w1lo : g_w2lo;
            int j = i & 16383;
            int k = j >> 7, n = j & 127;                             // B[n][k] = w[k][n]
            float v = w[j];
            __nv_bfloat16 h = __float2bfloat16(v);
            __nv_bfloat16 l = __float2bfloat16(v - __bfloat162float(h));
            uint32_t a = tile_addr(n, k);
            *(__nv_bfloat16*)((char*)hi + a) = h;
            *(__nv_bfloat16*)((char*)lo + a) = l;
        }
        return;
    }
    __shared__ int sh[SCAN_B];
    int tid = threadIdx.x;
    int i   = blockIdx.x * SCAN_B + tid;
    int v   = (i < N_NODES) ? g_degi[i] : 0;
    if (i < N_NODES) g_dinv[i] = rsqrtf((float)v + 1.f);
    sh[tid] = v;
    __syncthreads();
#pragma unroll
    for (int off = 1; off < SCAN_B; off <<= 1) {
        int t = (tid >= off) ? sh[tid - off] : 0;
        __syncthreads();
        sh[tid] += t;
        __syncthreads();
    }
    if (i < N_NODES) g_rows[i] = sh[tid] - v;
    if (tid == SCAN_B - 1) g_bsum[blockIdx.x] = sh[tid];
}

// scan phase 2+3 merged: each block re-derives its own block offset
__global__ __launch_bounds__(SCAN_B) void k_scan3() {
    __shared__ int sh[NSCANB];
    __shared__ int boff;
    int tid = threadIdx.x;
    if (tid < NSCANB) sh[tid] = g_bsum[tid];
    __syncthreads();
    if (tid == 0) {
        int s = 0;
        for (int j = 0; j < (int)blockIdx.x; j++) s += sh[j];
        boff = s;
    }
    __syncthreads();
    int i = blockIdx.x * SCAN_B + tid;
    if (i < N_NODES) {
        int rs = g_rows[i] + boff;
        g_rowstart[i] = rs;
        g_cursor[i]   = rs;
    }
    if (i == 0) g_rowstart[N_NODES] = E_EDGES;
}

__global__ void k_fill() {
    int e = blockIdx.x * blockDim.x + threadIdx.x;
    if (e >= E_EDGES) return;
    int s = g_src[e];
    int d = g_dst[e];
    int pos = atomicAdd(&g_cursor[d], 1);
    g_csrc[pos] = s;
    g_cw[pos]   = g_dinv[s];
}

// ---------------- HMMA GEMM: H16[N,128] = fp16( (relu?)A[N,128] @ W ) ---------
#define SM_AHI  0
#define SM_ALO  32768
#define SM_BHI  65536
#define SM_BLO  98304
#define SM_TOT  131072

template <bool RELU_IN>
__global__ __launch_bounds__(256)
void k_gemm_mma(const float* __restrict__ A,
                const __nv_bfloat16* __restrict__ Whi,
                const __nv_bfloat16* __restrict__ Wlo,
                __half* __restrict__ H16) {
    extern __shared__ char smem[];
    const uint32_t sbase = smem_u32(smem);
    const int tid  = threadIdx.x;
    const int wid  = tid >> 5;
    const int lane = tid & 31;
    const int rowBase = blockIdx.x * 128;

#pragma unroll
    for (int i = 0; i < 8; i++) {
        int idx = i * 256 + tid;
        ((uint4*)(smem + SM_BHI))[idx] = ((const uint4*)Whi)[idx];
        ((uint4*)(smem + SM_BLO))[idx] = ((const uint4*)Wlo)[idx];
    }

#pragma unroll
    for (int i = 0; i < 16; i++) {
        int f4  = i * 256 + tid;
        int row = f4 >> 5;
        int c4  = f4 & 31;
        int gr  = rowBase + row;
        float4 v = make_float4(0.f, 0.f, 0.f, 0.f);
        if (gr < N_NODES) v = *(const float4*)(A + (size_t)gr * HDIM + c4 * 4);
        if (RELU_IN) {
            v.x = fmaxf(v.x, 0.f); v.y = fmaxf(v.y, 0.f);
            v.z = fmaxf(v.z, 0.f); v.w = fmaxf(v.w, 0.f);
        }
        __nv_bfloat162 h01 = __floats2bfloat162_rn(v.x, v.y);
        __nv_bfloat162 h23 = __floats2bfloat162_rn(v.z, v.w);
        float2 f01 = __bfloat1622float2(h01);
        float2 f23 = __bfloat1622float2(h23);
        __nv_bfloat162 l01 = __floats2bfloat162_rn(v.x - f01.x, v.y - f01.y);
        __nv_bfloat162 l23 = __floats2bfloat162_rn(v.z - f23.x, v.w - f23.y);
        uint32_t addr = tile_addr(row, c4 * 4);
        uint2 uh, ul;
        uh.x = *(uint32_t*)&h01; uh.y = *(uint32_t*)&h23;
        ul.x = *(uint32_t*)&l01; ul.y = *(uint32_t*)&l23;
        *(uint2*)(smem + SM_AHI + addr) = uh;
        *(uint2*)(smem + SM_ALO + addr) = ul;
    }
    __syncthreads();

    float acc[16][4];
#pragma unroll
    for (int i = 0; i < 16; i++)
#pragma unroll
        for (int j = 0; j < 4; j++) acc[i][j] = 0.f;

    const int mb0 = wid * 2;
    const int ablk = lane >> 3;
    const int arow = lane & 7;
    const int a_mblk  = mb0 + (ablk & 1);
    const int a_khalf = ablk >> 1;
    const int b_noff  = ablk >> 1;
    const int b_khalf = ablk & 1;

#pragma unroll
    for (int k16 = 0; k16 < 8; k16++) {
        uint32_t a_addr = sbase + (uint32_t)((((a_mblk * 8 + k16) * 2 + a_khalf) * 128) + arow * 16);
        uint32_t ahi[4], alo[4];
        ldsm4(ahi, a_addr + SM_AHI);
        ldsm4(alo, a_addr + SM_ALO);

#pragma unroll
        for (int nb2 = 0; nb2 < 8; nb2++) {
            int nblk = nb2 * 2 + b_noff;
            uint32_t b_addr = sbase + (uint32_t)((((nblk * 8 + k16) * 2 + b_khalf) * 128) + arow * 16);
            uint32_t bh[4], bl[4];
            ldsm4(bh, b_addr + SM_BHI);
            ldsm4(bl, b_addr + SM_BLO);
            mma_bf16(acc[nb2 * 2],     ahi, bh[0], bh[1]);
            mma_bf16(acc[nb2 * 2],     ahi, bl[0], bl[1]);
            mma_bf16(acc[nb2 * 2],     alo, bh[0], bh[1]);
            mma_bf16(acc[nb2 * 2 + 1], ahi, bh[2], bh[3]);
            mma_bf16(acc[nb2 * 2 + 1], ahi, bl[2], bl[3]);
            mma_bf16(acc[nb2 * 2 + 1], alo, bh[2], bh[3]);
        }
    }

    // epilogue: fp16 output only (single consumer = gather)
    int g = lane >> 2;
    int q = lane & 3;
    int r0 = rowBase + wid * 16 + g;
    int r1 = r0 + 8;
#pragma unroll
    for (int nb = 0; nb < 16; nb++) {
        int col = nb * 8 + q * 2;
        if (r0 < N_NODES)
            *(__half2*)(H16 + (size_t)r0 * HDIM + col) = __floats2half2_rn(acc[nb][0], acc[nb][1]);
        if (r1 < N_NODES)
            *(__half2*)(H16 + (size_t)r1 * HDIM + col) = __floats2half2_rn(acc[nb][2], acc[nb][3]);
    }
}

// ---------------- gather-side aggregation (fp16 h) ----------------------------
// one warp per node; lane covers 4 cols (8B fp16). fp32 accumulation.
__device__ __forceinline__ void acc_row(float4& acc, uint2 u, float w) {
    float2 p0 = __half22float2(*(const __half2*)&u.x);
    float2 p1 = __half22float2(*(const __half2*)&u.y);
    acc.x = fmaf(p0.x, w, acc.x); acc.y = fmaf(p0.y, w, acc.y);
    acc.z = fmaf(p1.x, w, acc.z); acc.w = fmaf(p1.y, w, acc.w);
}

__global__ __launch_bounds__(256) void k_agg(const float* __restrict__ bias) {
    int w    = (blockIdx.x * blockDim.x + threadIdx.x) >> 5;
    int lane = threadIdx.x & 31;
    if (w >= N_NODES) return;

    int beg = g_rowstart[w];
    int end = g_rowstart[w + 1];
    const uint2* h16 = (const uint2*)g_h16;          // 8B units, 32 per row

    float4 acc = make_float4(0.f, 0.f, 0.f, 0.f);
    int e = beg;
    for (; e + 1 < end; e += 2) {
        int   s0 = g_csrc[e];     int   s1 = g_csrc[e + 1];
        float w0 = g_cw[e];       float w1 = g_cw[e + 1];
        uint2 u0 = h16[(size_t)s0 * 32 + lane];
        uint2 u1 = h16[(size_t)s1 * 32 + lane];
        acc_row(acc, u0, w0);
        acc_row(acc, u1, w1);
    }
    if (e < end) {
        uint2 u0 = h16[(size_t)g_csrc[e] * 32 + lane];
        acc_row(acc, u0, g_cw[e]);
    }

    float di = g_dinv[w];
    uint2 us = h16[(size_t)w * 32 + lane];
    float2 s0 = __half22float2(*(const __half2*)&us.x);
    float2 s1 = __half22float2(*(const __half2*)&us.y);
    float4 b4 = ((const float4*)bias)[lane];
    float4 o;
    o.x = fmaf(fmaf(s0.x, di, acc.x), di, b4.x);
    o.y = fmaf(fmaf(s0.y, di, acc.y), di, b4.y);
    o.z = fmaf(fmaf(s1.x, di, acc.z), di, b4.z);
    o.w = fmaf(fmaf(s1.y, di, acc.w), di, b4.w);
    ((float4*)(g_a + (size_t)w * HDIM))[lane] = o;
}

// ---------------- readout ------------------------------------------------------
__global__ void k_readout(const float* __restrict__ fcw,
                          const float* __restrict__ fcb,
                          float* __restrict__ out) {
    int t   = threadIdx.x;                 // 128 threads
    int beg = g_rowstart[0];
    int end = g_rowstart[1];
    float sum = 0.f;
    for (int e = beg; e < end; e++) {
        int s = g_csrc[e];
        sum += fmaxf(g_a[(size_t)s * HDIM + t], 0.f);
    }
    float cnt = fmaxf((float)(end - beg), 1.f);
    float v = fmaxf(g_a[t], 0.f) * fcw[t] + (sum / cnt) * fcw[HDIM + t];
#pragma unroll
    for (int off = 16; off > 0; off >>= 1)
        v += __shfl_xor_sync(0xFFFFFFFFu, v, off);
    __shared__ float red[4];
    if ((t & 31) == 0) red[t >> 5] = v;
    __syncthreads();
    if (t == 0) out[0] = red[0] + red[1] + red[2] + red[3] + fcb[0];
}

// ---------------- launcher -------------------------------------------------------
extern "C" void kernel_launch(void* const* d_in, const int* in_sizes, int n_in,
                              void* d_out, int out_size) {
    const float* x   = nullptr;
    const void*  ei  = nullptr;
    const float* w1  = nullptr;
    const float* b1  = nullptr;
    const float* w2  = nullptr;
    const float* b2  = nullptr;
    const float* fcw = nullptr;
    const float* fcb = nullptr;
    for (int i = 0; i < n_in; i++) {
        switch (in_sizes[i]) {
            case 12800000: x   = (const float*)d_in[i];     break;
            case 3200000:  ei  = d_in[i];                   break;
            case 100000:   break;
            case 16384:    if (!w1) w1 = (const float*)d_in[i];
                           else      w2 = (const float*)d_in[i]; break;
            case 128:      if (!b1) b1 = (const float*)d_in[i];
                           else      b2 = (const float*)d_in[i]; break;
            case 256:      fcw = (const float*)d_in[i];     break;
            case 1:        fcb = (const float*)d_in[i];     break;
            default: break;
        }
    }
    float* out = (float*)d_out;

    float *p_a = nullptr;
    __half *p_h16 = nullptr;
    __nv_bfloat16 *p_w1hi = nullptr, *p_w1lo = nullptr, *p_w2hi = nullptr, *p_w2lo = nullptr;
    cudaGetSymbolAddress((void**)&p_a, g_a);
    cudaGetSymbolAddress((void**)&p_h16, g_h16);
    cudaGetSymbolAddress((void**)&p_w1hi, g_w1hi);
    cudaGetSymbolAddress((void**)&p_w1lo, g_w1lo);
    cudaGetSymbolAddress((void**)&p_w2hi, g_w2hi);
    cudaGetSymbolAddress((void**)&p_w2lo, g_w2lo);

    cudaFuncSetAttribute(k_gemm_mma<false>, cudaFuncAttributeMaxDynamicSharedMemorySize, SM_TOT);
    cudaFuncSetAttribute(k_gemm_mma<true>,  cudaFuncAttributeMaxDynamicSharedMemorySize, SM_TOT);

    const int TB = 256;
    const int gN    = (N_NODES + TB - 1) / TB;
    const int gE    = (E_EDGES + TB - 1) / TB;
    const int gTile = (N_NODES + 127) / 128;          // 782
    const int gAgg  = (N_NODES * 32 + TB - 1) / TB;

    // CSR build + weight conversion
    k_init <<<gN, TB>>>((const long long*)ei);
    k_prep <<<gE, TB>>>(ei);
    k_scan1<<<NSCANB + 32, SCAN_B>>>(w1, w2);
    k_scan3<<<NSCANB, SCAN_B>>>();
    k_fill <<<gE, TB>>>();

    // layer 1
    k_gemm_mma<false><<<gTile, TB, SM_TOT>>>(x, p_w1hi, p_w1lo, p_h16);
    k_agg<<<gAgg, TB>>>(b1);

    // layer 2 (relu fused into A conversion)
    k_gemm_mma<true><<<gTile, TB, SM_TOT>>>(p_a, p_w2hi, p_w2lo, p_h16);
    k_agg<<<gAgg, TB>>>(b2);

    // readout
    k_readout<<<1, 128>>>(fcw, fcb, out);
}

// round 9
// speedup vs baseline: 1.5394x; 1.1611x over previous
#include <cuda_runtime.h>
#include <cuda_bf16.h>
#include <cuda_fp16.h>
#include <cstdint>

#define N_NODES 100000
#define E_EDGES 1600000
#define HDIM    128
#define SCAN_B  1024
#define NSCANB  ((N_NODES + SCAN_B - 1) / SCAN_B)   // 98

// ---------------- scratch (static device globals; no runtime allocation) ----
__device__ int   g_is64;
__device__ int   g_degi[N_NODES];
__device__ float g_dinv[N_NODES];
__device__ int   g_rows[N_NODES];
__device__ int   g_bsum[NSCANB];
__device__ int   g_rowstart[N_NODES + 1];
__device__ int   g_cursor[N_NODES];
__device__ int   g_csrc[E_EDGES];
__device__ float g_cw  [E_EDGES];
__device__ __align__(16) __half g_h16[(size_t)N_NODES * HDIM];  // GEMM out (fp16)
__device__ __align__(16) __half g_a16[(size_t)N_NODES * HDIM];  // agg1 out (fp16)
__device__ float g_nbuf[HDIM];   // neighbor relu-sum (layer 2, sparse)
__device__ float g_tbuf[HDIM];   // target node a2
// pre-tiled bf16 weight images (exact SMEM 8x8-block layout, 32KB each)
__device__ __align__(16) __nv_bfloat16 g_w1hi[16384];
__device__ __align__(16) __nv_bfloat16 g_w1lo[16384];
__device__ __align__(16) __nv_bfloat16 g_w2hi[16384];
__device__ __align__(16) __nv_bfloat16 g_w2lo[16384];

// ---------------- PTX helpers -------------------------------------------------
__device__ __forceinline__ uint32_t smem_u32(const void* p) {
    uint32_t a;
    asm("{ .reg .u64 t; cvta.to.shared.u64 t, %1; cvt.u32.u64 %0, t; }" : "=r"(a) : "l"(p));
    return a;
}
__device__ __forceinline__ void ldsm4(uint32_t* r, uint32_t addr) {
    asm volatile("ldmatrix.sync.aligned.m8n8.x4.shared.b16 {%0,%1,%2,%3}, [%4];"
                 : "=r"(r[0]), "=r"(r[1]), "=r"(r[2]), "=r"(r[3]) : "r"(addr));
}
__device__ __forceinline__ void mma_bf16(float* c, const uint32_t* a, uint32_t b0, uint32_t b1) {
    asm volatile("mma.sync.aligned.m16n8k16.row.col.f32.bf16.bf16.f32 "
                 "{%0,%1,%2,%3}, {%4,%5,%6,%7}, {%8,%9}, {%0,%1,%2,%3};"
                 : "+f"(c[0]), "+f"(c[1]), "+f"(c[2]), "+f"(c[3])
                 : "r"(a[0]), "r"(a[1]), "r"(a[2]), "r"(a[3]), "r"(b0), "r"(b1));
}

// 8x8-block tile layout (r = m or n index 0..127, k = 0..127)
__device__ __forceinline__ uint32_t tile_addr(int r, int k) {
    uint32_t blk = (uint32_t)(((r >> 3) * 8 + (k >> 4)) * 2 + ((k >> 3) & 1));
    return blk * 128 + (uint32_t)((r & 7) * 16 + (k & 7) * 2);
}

// edge decode (shared by k_prep / k_fill — must be identical)
__device__ __forceinline__ void edge_decode(const void* eiv, int e, int& s, int& d) {
    if (g_is64) {
        const long long* p = (const long long*)eiv;
        s = (int)p[e];
        d = (int)p[E_EDGES + e];
    } else {
        const int* p = (const int*)eiv;
        s = p[e];
        d = p[E_EDGES + e];
    }
    if ((unsigned)s >= N_NODES) s = 0;
    if ((unsigned)d >= N_NODES) d = 0;
}

// ---------------- prep / CSR build --------------------------------------------
__global__ void k_init(const long long* __restrict__ ei) {
    int i = blockIdx.x * blockDim.x + threadIdx.x;
    if (i < N_NODES) g_degi[i] = 0;
    if (i < HDIM)    g_nbuf[i] = 0.f;
    if (blockIdx.x == 0 && threadIdx.x == 0) {
        int is64 = 1;
#pragma unroll
        for (int j = 0; j < 16; j++) {
            long long v = ei[j];
            if (v < 0 || v >= N_NODES) { is64 = 0; break; }
        }
        g_is64 = is64;
    }
}

__global__ void k_prep(const void* __restrict__ eiv) {
    int e = blockIdx.x * blockDim.x + threadIdx.x;
    if (e >= E_EDGES) return;
    int s, d;
    edge_decode(eiv, e, s, d);
    atomicAdd(&g_degi[d], 1);
}

// scan phase 1 + weight conversion (merged grids; blocks >= NSCANB do wconv)
__global__ __launch_bounds__(SCAN_B) void k_scan1(const float* __restrict__ w1,
                                                  const float* __restrict__ w2) {
    if (blockIdx.x >= NSCANB) {
        int i = (int)(blockIdx.x - NSCANB) * SCAN_B + threadIdx.x;   // 0..32767
        if (i < 32768) {
            const float* w = (i < 16384) ? w1 : w2;
            __nv_bfloat16* hi = (i < 16384) ? g_w1hi : g_w2hi;
            __nv_bfloat16* lo = (i < 16384) ? g_w1lo : g_w2lo;
            int j = i & 16383;
            int k = j >> 7, n = j & 127;                             // B[n][k] = w[k][n]
            float v = w[j];
            __nv_bfloat16 h = __float2bfloat16(v);
            __nv_bfloat16 l = __float2bfloat16(v - __bfloat162float(h));
            uint32_t a = tile_addr(n, k);
            *(__nv_bfloat16*)((char*)hi + a) = h;
            *(__nv_bfloat16*)((char*)lo + a) = l;
        }
        return;
    }
    __shared__ int sh[SCAN_B];
    int tid = threadIdx.x;
    int i   = blockIdx.x * SCAN_B + tid;
    int v   = (i < N_NODES) ? g_degi[i] : 0;
    if (i < N_NODES) g_dinv[i] = rsqrtf((float)v + 1.f);
    sh[tid] = v;
    __syncthreads();
#pragma unroll
    for (int off = 1; off < SCAN_B; off <<= 1) {
        int t = (tid >= off) ? sh[tid - off] : 0;
        __syncthreads();
        sh[tid] += t;
        __syncthreads();
    }
    if (i < N_NODES) g_rows[i] = sh[tid] - v;
    if (tid == SCAN_B - 1) g_bsum[blockIdx.x] = sh[tid];
}

// scan phase 2+3 merged: parallel 128-wide scan of block sums, then offset apply
__global__ __launch_bounds__(SCAN_B) void k_scan3() {
    __shared__ int sh[128];
    int tid = threadIdx.x;
    if (tid < 128) sh[tid] = (tid < NSCANB) ? g_bsum[tid] : 0;
    __syncthreads();
#pragma unroll
    for (int off = 1; off < 128; off <<= 1) {
        int t = (tid < 128 && tid >= off) ? sh[tid - off] : 0;
        __syncthreads();
        if (tid < 128) sh[tid] += t;
        __syncthreads();
    }
    int boff = (blockIdx.x == 0) ? 0 : sh[blockIdx.x - 1];
    int i = blockIdx.x * SCAN_B + tid;
    if (i < N_NODES) {
        int rs = g_rows[i] + boff;
        g_rowstart[i] = rs;
        g_cursor[i]   = rs;
    }
    if (i == 0) g_rowstart[N_NODES] = E_EDGES;
}

__global__ void k_fill(const void* __restrict__ eiv) {
    int e = blockIdx.x * blockDim.x + threadIdx.x;
    if (e >= E_EDGES) return;
    int s, d;
    edge_decode(eiv, e, s, d);
    int pos = atomicAdd(&g_cursor[d], 1);
    g_csrc[pos] = s;
    g_cw[pos]   = g_dinv[s];
}

// ---------------- HMMA GEMM: H16[N,128] = fp16( (relu?)A[N,128] @ W ) ---------
#define SM_AHI  0
#define SM_ALO  32768
#define SM_BHI  65536
#define SM_BLO  98304
#define SM_TOT  131072

__device__ __forceinline__ float4 loadA4(const float* A, size_t off) {
    return *(const float4*)(A + off);
}
__device__ __forceinline__ float4 loadA4(const __half* A, size_t off) {
    uint2 u = *(const uint2*)(A + off);
    float2 a = __half22float2(*(const __half2*)&u.x);
    float2 b = __half22float2(*(const __half2*)&u.y);
    return make_float4(a.x, a.y, b.x, b.y);
}

template <bool RELU_IN, typename TA>
__global__ __launch_bounds__(256)
void k_gemm_mma(const TA* __restrict__ A,
                const __nv_bfloat16* __restrict__ Whi,
                const __nv_bfloat16* __restrict__ Wlo,
                __half* __restrict__ H16) {
    extern __shared__ char smem[];
    const uint32_t sbase = smem_u32(smem);
    const int tid  = threadIdx.x;
    const int wid  = tid >> 5;
    const int lane = tid & 31;
    const int rowBase = blockIdx.x * 128;

#pragma unroll
    for (int i = 0; i < 8; i++) {
        int idx = i * 256 + tid;
        ((uint4*)(smem + SM_BHI))[idx] = ((const uint4*)Whi)[idx];
        ((uint4*)(smem + SM_BLO))[idx] = ((const uint4*)Wlo)[idx];
    }

#pragma unroll
    for (int i = 0; i < 16; i++) {
        int f4  = i * 256 + tid;
        int row = f4 >> 5;
        int c4  = f4 & 31;
        int gr  = rowBase + row;
        float4 v = make_float4(0.f, 0.f, 0.f, 0.f);
        if (gr < N_NODES) v = loadA4(A, (size_t)gr * HDIM + c4 * 4);
        if (RELU_IN) {
            v.x = fmaxf(v.x, 0.f); v.y = fmaxf(v.y, 0.f);
            v.z = fmaxf(v.z, 0.f); v.w = fmaxf(v.w, 0.f);
        }
        __nv_bfloat162 h01 = __floats2bfloat162_rn(v.x, v.y);
        __nv_bfloat162 h23 = __floats2bfloat162_rn(v.z, v.w);
        float2 f01 = __bfloat1622float2(h01);
        float2 f23 = __bfloat1622float2(h23);
        __nv_bfloat162 l01 = __floats2bfloat162_rn(v.x - f01.x, v.y - f01.y);
        __nv_bfloat162 l23 = __floats2bfloat162_rn(v.z - f23.x, v.w - f23.y);
        uint32_t addr = tile_addr(row, c4 * 4);
        uint2 uh, ul;
        uh.x = *(uint32_t*)&h01; uh.y = *(uint32_t*)&h23;
        ul.x = *(uint32_t*)&l01; ul.y = *(uint32_t*)&l23;
        *(uint2*)(smem + SM_AHI + addr) = uh;
        *(uint2*)(smem + SM_ALO + addr) = ul;
    }
    __syncthreads();

    float acc[16][4];
#pragma unroll
    for (int i = 0; i < 16; i++)
#pragma unroll
        for (int j = 0; j < 4; j++) acc[i][j] = 0.f;

    const int mb0 = wid * 2;
    const int ablk = lane >> 3;
    const int arow = lane & 7;
    const int a_mblk  = mb0 + (ablk & 1);
    const int a_khalf = ablk >> 1;
    const int b_noff  = ablk >> 1;
    const int b_khalf = ablk & 1;

#pragma unroll
    for (int k16 = 0; k16 < 8; k16++) {
        uint32_t a_addr = sbase + (uint32_t)((((a_mblk * 8 + k16) * 2 + a_khalf) * 128) + arow * 16);
        uint32_t ahi[4], alo[4];
        ldsm4(ahi, a_addr + SM_AHI);
        ldsm4(alo, a_addr + SM_ALO);

#pragma unroll
        for (int nb2 = 0; nb2 < 8; nb2++) {
            int nblk = nb2 * 2 + b_noff;
            uint32_t b_addr = sbase + (uint32_t)((((nblk * 8 + k16) * 2 + b_khalf) * 128) + arow * 16);
            uint32_t bh[4], bl[4];
            ldsm4(bh, b_addr + SM_BHI);
            ldsm4(bl, b_addr + SM_BLO);
            mma_bf16(acc[nb2 * 2],     ahi, bh[0], bh[1]);
            mma_bf16(acc[nb2 * 2],     ahi, bl[0], bl[1]);
            mma_bf16(acc[nb2 * 2],     alo, bh[0], bh[1]);
            mma_bf16(acc[nb2 * 2 + 1], ahi, bh[2], bh[3]);
            mma_bf16(acc[nb2 * 2 + 1], ahi, bl[2], bl[3]);
            mma_bf16(acc[nb2 * 2 + 1], alo, bh[2], bh[3]);
        }
    }

    int g = lane >> 2;
    int q = lane & 3;
    int r0 = rowBase + wid * 16 + g;
    int r1 = r0 + 8;
#pragma unroll
    for (int nb = 0; nb < 16; nb++) {
        int col = nb * 8 + q * 2;
        if (r0 < N_NODES)
            *(__half2*)(H16 + (size_t)r0 * HDIM + col) = __floats2half2_rn(acc[nb][0], acc[nb][1]);
        if (r1 < N_NODES)
            *(__half2*)(H16 + (size_t)r1 * HDIM + col) = __floats2half2_rn(acc[nb][2], acc[nb][3]);
    }
}

// ---------------- layer-1 aggregation (fp16 h -> fp16 a) ----------------------
__device__ __forceinline__ void acc_row(float4& acc, uint2 u, float w) {
    float2 p0 = __half22float2(*(const __half2*)&u.x);
    float2 p1 = __half22float2(*(const __half2*)&u.y);
    acc.x = fmaf(p0.x, w, acc.x); acc.y = fmaf(p0.y, w, acc.y);
    acc.z = fmaf(p1.x, w, acc.z); acc.w = fmaf(p1.y, w, acc.w);
}

__global__ __launch_bounds__(256) void k_agg(const float* __restrict__ bias) {
    int w    = (blockIdx.x * blockDim.x + threadIdx.x) >> 5;
    int lane = threadIdx.x & 31;
    if (w >= N_NODES) return;

    int beg = g_rowstart[w];
    int end = g_rowstart[w + 1];
    const uint2* h16 = (const uint2*)g_h16;          // 8B units, 32 per row

    float4 acc = make_float4(0.f, 0.f, 0.f, 0.f);
    int e = beg;
    for (; e + 1 < end; e += 2) {
        int   s0 = g_csrc[e];     int   s1 = g_csrc[e + 1];
        float w0 = g_cw[e];       float w1 = g_cw[e + 1];
        uint2 u0 = h16[(size_t)s0 * 32 + lane];
        uint2 u1 = h16[(size_t)s1 * 32 + lane];
        acc_row(acc, u0, w0);
        acc_row(acc, u1, w1);
    }
    if (e < end) {
        uint2 u0 = h16[(size_t)g_csrc[e] * 32 + lane];
        acc_row(acc, u0, g_cw[e]);
    }

    float di = g_dinv[w];
    uint2 us = h16[(size_t)w * 32 + lane];
    float2 s0 = __half22float2(*(const __half2*)&us.x);
    float2 s1 = __half22float2(*(const __half2*)&us.y);
    float4 b4 = ((const float4*)bias)[lane];
    float4 o;
    o.x = fmaf(fmaf(s0.x, di, acc.x), di, b4.x);
    o.y = fmaf(fmaf(s0.y, di, acc.y), di, b4.y);
    o.z = fmaf(fmaf(s1.x, di, acc.z), di, b4.z);
    o.w = fmaf(fmaf(s1.y, di, acc.w), di, b4.w);
    __half2 o01 = __floats2half2_rn(o.x, o.y);
    __half2 o23 = __floats2half2_rn(o.z, o.w);
    uint2 st;
    st.x = *(uint32_t*)&o01;
    st.y = *(uint32_t*)&o23;
    ((uint2*)(g_a16 + (size_t)w * HDIM))[lane] = st;
}

// ---------------- sparse layer-2 aggregation + readout -------------------------
// a2[v] (pre-relu) for the tiny set of needed nodes, from GEMM2's fp16 output.
__device__ __forceinline__ float agg_node2(int v, int t, const float* b2) {
    int beg = g_rowstart[v];
    int end = g_rowstart[v + 1];
    float acc = 0.f;
    int e = beg;
    for (; e + 1 < end; e += 2) {
        float h0 = __half2float(g_h16[(size_t)g_csrc[e]     * HDIM + t]);
        float h1 = __half2float(g_h16[(size_t)g_csrc[e + 1] * HDIM + t]);
        acc = fmaf(h0, g_cw[e], acc);
        acc = fmaf(h1, g_cw[e + 1], acc);
    }
    if (e < end)
        acc = fmaf(__half2float(g_h16[(size_t)g_csrc[e] * HDIM + t]), g_cw[e], acc);
    float di = g_dinv[v];
    acc = fmaf(__half2float(g_h16[(size_t)v * HDIM + t]), di, acc);
    return fmaf(acc, di, b2[t]);
}

__global__ __launch_bounds__(128) void k_spagg(const float* __restrict__ b2) {
    int b = blockIdx.x;          // block 0 -> target node; others -> edges of row 0
    int t = threadIdx.x;         // 128 threads = dims
    if (b == 0) {
        g_tbuf[t] = agg_node2(0, t, b2);
        return;
    }
    int beg = g_rowstart[0];
    int cnt = g_rowstart[1] - beg;
    for (int j = b - 1; j < cnt; j += (int)gridDim.x - 1) {
        int v = g_csrc[beg + j];
        float av = fmaxf(agg_node2(v, t, b2), 0.f);
        atomicAdd(&g_nbuf[t], av);
    }
}

__global__ void k_final(const float* __restrict__ fcw,
                        const float* __restrict__ fcb,
                        float* __restrict__ out) {
    int t = threadIdx.x;   // 128 threads
    float cnt = fmaxf((float)(g_rowstart[1] - g_rowstart[0]), 1.f);
    float v = fmaxf(g_tbuf[t], 0.f) * fcw[t] + (g_nbuf[t] / cnt) * fcw[HDIM + t];
#pragma unroll
    for (int off = 16; off > 0; off >>= 1)
        v += __shfl_xor_sync(0xFFFFFFFFu, v, off);
    __shared__ float red[4];
    if ((t & 31) == 0) red[t >> 5] = v;
    __syncthreads();
    if (t == 0) out[0] = red[0] + red[1] + red[2] + red[3] + fcb[0];
}

// ---------------- launcher -------------------------------------------------------
extern "C" void kernel_launch(void* const* d_in, const int* in_sizes, int n_in,
                              void* d_out, int out_size) {
    const float* x   = nullptr;
    const void*  ei  = nullptr;
    const float* w1  = nullptr;
    const float* b1  = nullptr;
    const float* w2  = nullptr;
    const float* b2  = nullptr;
    const float* fcw = nullptr;
    const float* fcb = nullptr;
    for (int i = 0; i < n_in; i++) {
        switch (in_sizes[i]) {
            case 12800000: x   = (const float*)d_in[i];     break;
            case 3200000:  ei  = d_in[i];                   break;
            case 100000:   break;
            case 16384:    if (!w1) w1 = (const float*)d_in[i];
                           else      w2 = (const float*)d_in[i]; break;
            case 128:      if (!b1) b1 = (const float*)d_in[i];
                           else      b2 = (const float*)d_in[i]; break;
            case 256:      fcw = (const float*)d_in[i];     break;
            case 1:        fcb = (const float*)d_in[i];     break;
            default: break;
        }
    }
    float* out = (float*)d_out;

    __half *p_h16 = nullptr, *p_a16 = nullptr;
    __nv_bfloat16 *p_w1hi = nullptr, *p_w1lo = nullptr, *p_w2hi = nullptr, *p_w2lo = nullptr;
    cudaGetSymbolAddress((void**)&p_h16, g_h16);
    cudaGetSymbolAddress((void**)&p_a16, g_a16);
    cudaGetSymbolAddress((void**)&p_w1hi, g_w1hi);
    cudaGetSymbolAddress((void**)&p_w1lo, g_w1lo);
    cudaGetSymbolAddress((void**)&p_w2hi, g_w2hi);
    cudaGetSymbolAddress((void**)&p_w2lo, g_w2lo);

    cudaFuncSetAttribute(k_gemm_mma<false, float>,  cudaFuncAttributeMaxDynamicSharedMemorySize, SM_TOT);
    cudaFuncSetAttribute(k_gemm_mma<true,  __half>, cudaFuncAttributeMaxDynamicSharedMemorySize, SM_TOT);

    const int TB = 256;
    const int gN    = (N_NODES + TB - 1) / TB;
    const int gE    = (E_EDGES + TB - 1) / TB;
    const int gTile = (N_NODES + 127) / 128;          // 782
    const int gAgg  = (N_NODES * 32 + TB - 1) / TB;

    // CSR build + weight conversion
    k_init <<<gN, TB>>>((const long long*)ei);
    k_prep <<<gE, TB>>>(ei);
    k_scan1<<<NSCANB + 32, SCAN_B>>>(w1, w2);
    k_scan3<<<NSCANB, SCAN_B>>>();
    k_fill <<<gE, TB>>>(ei);

    // layer 1
    k_gemm_mma<false, float><<<gTile, TB, SM_TOT>>>(x, p_w1hi, p_w1lo, p_h16);
    k_agg<<<gAgg, TB>>>(b1);

    // layer 2: full GEMM (needed at neighbors' neighbors), sparse aggregation
    k_gemm_mma<true, __half><<<gTile, TB, SM_TOT>>>(p_a16, p_w2hi, p_w2lo, p_h16);
    k_spagg<<<33, 128>>>(b2);

    // readout
    k_final<<<1, 128>>>(fcw, fcb, out);
}

// round 10
// speedup vs baseline: 3.3740x; 2.1918x over previous
#include <cuda_runtime.h>
#include <cuda_bf16.h>
#include <cstdint>

#define N_NODES 100000
#define E_EDGES 1600000
#define HDIM    128
#define BMW     ((N_NODES + 31) / 32)     // 3125 bitmap words

#define CAP_V2   64
#define CAP_EV2  256
#define CAP_H2   4096
#define CAP_EB2  8192
#define CAP_H1   65536
#define CAP_EB1  131072

// ---------------- scratch (static device globals) ------------------------------
__device__ int      g_is64;
__device__ int      g_degi[N_NODES];
__device__ float    g_dinv[N_NODES];
__device__ uint32_t g_bmV2[BMW], g_bmH2[BMW], g_bmH1[BMW];
__device__ int      g_slotV2[N_NODES], g_slotH2[N_NODES], g_slotH1[N_NODES];
__device__ int      g_LV2[CAP_V2], g_LH2[CAP_H2], g_LH1[CAP_H1];
__device__ int      g_EV2[CAP_EV2];
__device__ int2     g_EB1[CAP_EB1], g_EB2[CAP_EB2];
__device__ int      g_cntV2, g_cntEV2, g_cntH2, g_cntH1, g_cntEB1, g_cntEB2;
__device__ __align__(16) float g_h1s [(size_t)CAP_H1 * HDIM];  // h1 compact
__device__ __align__(16) float g_acc1[(size_t)CAP_H2 * HDIM];  // agg1 accum
__device__ __align__(16) float g_a1s [(size_t)CAP_H2 * HDIM];  // relu(a1) compact
__device__ __align__(16) float g_h2s [(size_t)CAP_H2 * HDIM];  // h2 compact
// pre-tiled bf16 weight images (exact SMEM 8x8-block layout, 32KB each)
__device__ __align__(16) __nv_bfloat16 g_w1hi[16384];
__device__ __align__(16) __nv_bfloat16 g_w1lo[16384];
__device__ __align__(16) __nv_bfloat16 g_w2hi[16384];
__device__ __align__(16) __nv_bfloat16 g_w2lo[16384];

// ---------------- PTX helpers ----------------------------------------------------
__device__ __forceinline__ uint32_t smem_u32(const void* p) {
    uint32_t a;
    asm("{ .reg .u64 t; cvta.to.shared.u64 t, %1; cvt.u32.u64 %0, t; }" : "=r"(a) : "l"(p));
    return a;
}
__device__ __forceinline__ void ldsm4(uint32_t* r, uint32_t addr) {
    asm volatile("ldmatrix.sync.aligned.m8n8.x4.shared.b16 {%0,%1,%2,%3}, [%4];"
                 : "=r"(r[0]), "=r"(r[1]), "=r"(r[2]), "=r"(r[3]) : "r"(addr));
}
__device__ __forceinline__ void mma_bf16(float* c, const uint32_t* a, uint32_t b0, uint32_t b1) {
    asm volatile("mma.sync.aligned.m16n8k16.row.col.f32.bf16.bf16.f32 "
                 "{%0,%1,%2,%3}, {%4,%5,%6,%7}, {%8,%9}, {%0,%1,%2,%3};"
                 : "+f"(c[0]), "+f"(c[1]), "+f"(c[2]), "+f"(c[3])
                 : "r"(a[0]), "r"(a[1]), "r"(a[2]), "r"(a[3]), "r"(b0), "r"(b1));
}
// 8x8-block tile layout (r = m/n 0..127, k = 0..127)
__device__ __forceinline__ uint32_t tile_addr(int r, int k) {
    uint32_t blk = (uint32_t)(((r >> 3) * 8 + (k >> 4)) * 2 + ((k >> 3) & 1));
    return blk * 128 + (uint32_t)((r & 7) * 16 + (k & 7) * 2);
}
__device__ __forceinline__ void edge_decode(const void* eiv, int e, int& s, int& d) {
    if (g_is64) {
        const long long* p = (const long long*)eiv;
        s = (int)p[e];
        d = (int)p[E_EDGES + e];
    } else {
        const int* p = (const int*)eiv;
        s = p[e];
        d = p[E_EDGES + e];
    }
    if ((unsigned)s >= N_NODES) s = 0;
    if ((unsigned)d >= N_NODES) d = 0;
}
__device__ __forceinline__ void try_append(uint32_t* bm, int* slotArr, int* list,
                                           int* cnt, int cap, int node) {
    uint32_t mask = 1u << (node & 31);
    uint32_t old = atomicOr(&bm[node >> 5], mask);
    if (!(old & mask)) {
        int s = atomicAdd(cnt, 1);
        if (s < cap) { slotArr[node] = s; list[s] = node; }
    }
}

// ---------------- init: zero + seed node 0 --------------------------------------
__global__ __launch_bounds__(1024) void k_init(const long long* __restrict__ ei) {
    int i = blockIdx.x * blockDim.x + threadIdx.x;   // 512 blocks x 1024 = 524288
    if (i < N_NODES) g_degi[i] = 0;
    if (i >= 1 && i < BMW) { g_bmV2[i] = 0; g_bmH2[i] = 0; g_bmH1[i] = 0; }
    if (i < CAP_H2 * HDIM) g_acc1[i] = 0.f;
    if (i == 0) {
        g_bmV2[0] = 1u; g_bmH2[0] = 1u; g_bmH1[0] = 1u;          // node 0 seeded
        g_slotV2[0] = 0; g_slotH2[0] = 0; g_slotH1[0] = 0;
        g_LV2[0] = 0;    g_LH2[0] = 0;   g_LH1[0] = 0;
        g_cntV2 = 1; g_cntH2 = 1; g_cntH1 = 1;
        g_cntEV2 = 0; g_cntEB1 = 0; g_cntEB2 = 0;
        int is64 = 1;
#pragma unroll
        for (int j = 0; j < 16; j++) {
            long long v = ei[j];
            if (v < 0 || v >= N_NODES) { is64 = 0; break; }
        }
        g_is64 = is64;
    }
}

// ---------------- pass 0: degree histogram + V2 frontier -------------------------
__global__ void k_prep(const void* __restrict__ eiv) {
    int e = blockIdx.x * blockDim.x + threadIdx.x;
    if (e >= E_EDGES) return;
    int s, d;
    edge_decode(eiv, e, s, d);
    atomicAdd(&g_degi[d], 1);
    if (d == 0) {
        int ev = atomicAdd(&g_cntEV2, 1);
        if (ev < CAP_EV2) g_EV2[ev] = s;
        try_append(g_bmV2, g_slotV2, g_LV2, &g_cntV2, CAP_V2, s);
        try_append(g_bmH2, g_slotH2, g_LH2, &g_cntH2, CAP_H2, s);
        try_append(g_bmH1, g_slotH1, g_LH1, &g_cntH1, CAP_H1, s);
    }
}

// ---------------- dinv + weight conversion (merged grids) ------------------------
__global__ __launch_bounds__(1024) void k_dw(const float* __restrict__ w1,
                                             const float* __restrict__ w2) {
    int blocksN = (N_NODES + 1023) / 1024;           // 98
    if ((int)blockIdx.x < blocksN) {
        int i = blockIdx.x * 1024 + threadIdx.x;
        if (i < N_NODES) g_dinv[i] = rsqrtf((float)g_degi[i] + 1.f);
        return;
    }
    int i = ((int)blockIdx.x - blocksN) * 1024 + threadIdx.x;   // 0..32767
    if (i < 32768) {
        const float* w = (i < 16384) ? w1 : w2;
        __nv_bfloat16* hi = (i < 16384) ? g_w1hi : g_w2hi;
        __nv_bfloat16* lo = (i < 16384) ? g_w1lo : g_w2lo;
        int j = i & 16383;
        int k = j >> 7, n = j & 127;                 // B[n][k] = w[k][n]
        float v = w[j];
        __nv_bfloat16 h = __float2bfloat16(v);
        __nv_bfloat16 l = __float2bfloat16(v - __bfloat162float(h));
        uint32_t a = tile_addr(n, k);
        *(__nv_bfloat16*)((char*)hi + a) = h;
        *(__nv_bfloat16*)((char*)lo + a) = l;
    }
}

// ---------------- pass 1: edges into V2 -> EB2, discover H2 ----------------------
__global__ void k_f1(const void* __restrict__ eiv) {
    int e = blockIdx.x * blockDim.x + threadIdx.x;
    if (e >= E_EDGES) return;
    int s, d;
    edge_decode(eiv, e, s, d);
    if (g_bmV2[d >> 5] & (1u << (d & 31))) {
        int i = atomicAdd(&g_cntEB2, 1);
        if (i < CAP_EB2) g_EB2[i] = make_int2(g_slotV2[d], s);
        try_append(g_bmH2, g_slotH2, g_LH2, &g_cntH2, CAP_H2, s);
        try_append(g_bmH1, g_slotH1, g_LH1, &g_cntH1, CAP_H1, s);
    }
}

// ---------------- pass 2: edges into H2 -> EB1, discover H1 ----------------------
__global__ void k_f2(const void* __restrict__ eiv) {
    int e = blockIdx.x * blockDim.x + threadIdx.x;
    if (e >= E_EDGES) return;
    int s, d;
    edge_decode(eiv, e, s, d);
    if (g_bmH2[d >> 5] & (1u << (d & 31))) {
        int i = atomicAdd(&g_cntEB1, 1);
        if (i < CAP_EB1) g_EB1[i] = make_int2(g_slotH2[d], s);
        try_append(g_bmH1, g_slotH1, g_LH1, &g_cntH1, CAP_H1, s);
    }
}

// ---------------- sparse HMMA GEMM: O[r] = A[idx?[r]] @ W (fp32 out) -------------
#define SM_AHI  0
#define SM_ALO  32768
#define SM_BHI  65536
#define SM_BLO  98304
#define SM_TOT  131072

template <bool GATHER>
__global__ __launch_bounds__(256)
void k_gemm_s(const float* __restrict__ A,
              const int* __restrict__ idx,
              const int* __restrict__ cntp, int cap,
              const __nv_bfloat16* __restrict__ Whi,
              const __nv_bfloat16* __restrict__ Wlo,
              float* __restrict__ O) {
    int cnt = *cntp; if (cnt > cap) cnt = cap;
    const int rowBase = blockIdx.x * 128;
    if (rowBase >= cnt) return;

    extern __shared__ char smem[];
    const uint32_t sbase = smem_u32(smem);
    const int tid  = threadIdx.x;
    const int wid  = tid >> 5;
    const int lane = tid & 31;

#pragma unroll
    for (int i = 0; i < 8; i++) {
        int k = i * 256 + tid;
        ((uint4*)(smem + SM_BHI))[k] = ((const uint4*)Whi)[k];
        ((uint4*)(smem + SM_BLO))[k] = ((const uint4*)Wlo)[k];
    }

#pragma unroll
    for (int i = 0; i < 16; i++) {
        int f4  = i * 256 + tid;
        int row = f4 >> 5;
        int c4  = f4 & 31;
        int r   = rowBase + row;
        float4 v = make_float4(0.f, 0.f, 0.f, 0.f);
        if (r < cnt) {
            int node = GATHER ? idx[r] : r;
            v = *(const float4*)(A + (size_t)node * HDIM + c4 * 4);
        }
        __nv_bfloat162 h01 = __floats2bfloat162_rn(v.x, v.y);
        __nv_bfloat162 h23 = __floats2bfloat162_rn(v.z, v.w);
        float2 f01 = __bfloat1622float2(h01);
        float2 f23 = __bfloat1622float2(h23);
        __nv_bfloat162 l01 = __floats2bfloat162_rn(v.x - f01.x, v.y - f01.y);
        __nv_bfloat162 l23 = __floats2bfloat162_rn(v.z - f23.x, v.w - f23.y);
        uint32_t addr = tile_addr(row, c4 * 4);
        uint2 uh, ul;
        uh.x = *(uint32_t*)&h01; uh.y = *(uint32_t*)&h23;
        ul.x = *(uint32_t*)&l01; ul.y = *(uint32_t*)&l23;
        *(uint2*)(smem + SM_AHI + addr) = uh;
        *(uint2*)(smem + SM_ALO + addr) = ul;
    }
    __syncthreads();

    float acc[16][4];
#pragma unroll
    for (int i = 0; i < 16; i++)
#pragma unroll
        for (int j = 0; j < 4; j++) acc[i][j] = 0.f;

    const int mb0 = wid * 2;
    const int ablk = lane >> 3;
    const int arow = lane & 7;
    const int a_mblk  = mb0 + (ablk & 1);
    const int a_khalf = ablk >> 1;
    const int b_noff  = ablk >> 1;
    const int b_khalf = ablk & 1;

#pragma unroll
    for (int k16 = 0; k16 < 8; k16++) {
        uint32_t a_addr = sbase + (uint32_t)((((a_mblk * 8 + k16) * 2 + a_khalf) * 128) + arow * 16);
        uint32_t ahi[4], alo[4];
        ldsm4(ahi, a_addr + SM_AHI);
        ldsm4(alo, a_addr + SM_ALO);
#pragma unroll
        for (int nb2 = 0; nb2 < 8; nb2++) {
            int nblk = nb2 * 2 + b_noff;
            uint32_t b_addr = sbase + (uint32_t)((((nblk * 8 + k16) * 2 + b_khalf) * 128) + arow * 16);
            uint32_t bh[4], bl[4];
            ldsm4(bh, b_addr + SM_BHI);
            ldsm4(bl, b_addr + SM_BLO);
            mma_bf16(acc[nb2 * 2],     ahi, bh[0], bh[1]);
            mma_bf16(acc[nb2 * 2],     ahi, bl[0], bl[1]);
            mma_bf16(acc[nb2 * 2],     alo, bh[0], bh[1]);
            mma_bf16(acc[nb2 * 2 + 1], ahi, bh[2], bh[3]);
            mma_bf16(acc[nb2 * 2 + 1], ahi, bl[2], bl[3]);
            mma_bf16(acc[nb2 * 2 + 1], alo, bh[2], bh[3]);
        }
    }

    int g = lane >> 2;
    int q = lane & 3;
    int r0 = rowBase + wid * 16 + g;
    int r1 = r0 + 8;
#pragma unroll
    for (int nb = 0; nb < 16; nb++) {
        int col = nb * 8 + q * 2;
        if (r0 < cnt) *(float2*)(O + (size_t)r0 * HDIM + col) = make_float2(acc[nb][0], acc[nb][1]);
        if (r1 < cnt) *(float2*)(O + (size_t)r1 * HDIM + col) = make_float2(acc[nb][2], acc[nb][3]);
    }
}

// ---------------- agg1: acc1[slot] += dinv[src] * h1s[slotH1[src]] ---------------
__global__ __launch_bounds__(256) void k_agg1() {
    int gw   = (blockIdx.x * blockDim.x + threadIdx.x) >> 5;
    int lane = threadIdx.x & 31;
    int nw   = (gridDim.x * blockDim.x) >> 5;
    int cnt  = g_cntEB1; if (cnt > CAP_EB1) cnt = CAP_EB1;
    for (int i = gw; i < cnt; i += nw) {
        int2 e  = g_EB1[i];
        float w = g_dinv[e.y];
        int   r = g_slotH1[e.y];
        float4 v = ((const float4*)(g_h1s + (size_t)r * HDIM))[lane];
        float* dst = g_acc1 + (size_t)e.x * HDIM + lane * 4;
        atomicAdd(dst + 0, v.x * w);
        atomicAdd(dst + 1, v.y * w);
        atomicAdd(dst + 2, v.z * w);
        atomicAdd(dst + 3, v.w * w);
    }
}

// ---------------- a1 finalize: a1s = relu((acc1 + h1[v]*di)*di + b1) -------------
__global__ __launch_bounds__(256) void k_a1fin(const float* __restrict__ b1) {
    int gw   = (blockIdx.x * blockDim.x + threadIdx.x) >> 5;
    int lane = threadIdx.x & 31;
    int nw   = (gridDim.x * blockDim.x) >> 5;
    int cnt  = g_cntH2; if (cnt > CAP_H2) cnt = CAP_H2;
    for (int s = gw; s < cnt; s += nw) {
        int   v  = g_LH2[s];
        float di = g_dinv[v];
        float4 self = ((const float4*)(g_h1s + (size_t)g_slotH1[v] * HDIM))[lane];
        float4 ac   = ((const float4*)(g_acc1 + (size_t)s * HDIM))[lane];
        float4 b4   = ((const float4*)b1)[lane];
        float4 o;
        o.x = fmaxf(fmaf(fmaf(self.x, di, ac.x), di, b4.x), 0.f);
        o.y = fmaxf(fmaf(fmaf(self.y, di, ac.y), di, b4.y), 0.f);
        o.z = fmaxf(fmaf(fmaf(self.z, di, ac.z), di, b4.z), 0.f);
        o.w = fmaxf(fmaf(fmaf(self.w, di, ac.w), di, b4.w), 0.f);
        ((float4*)(g_a1s + (size_t)s * HDIM))[lane] = o;
    }
}

// ---------------- final: agg2 (V2 only) + readout --------------------------------
__global__ __launch_bounds__(512) void k_final(const float* __restrict__ b2,
                                               const float* __restrict__ fcw,
                                               const float* __restrict__ fcb,
                                               float* __restrict__ out) {
    __shared__ float sa[CAP_V2 * HDIM];   // 32KB
    __shared__ float sred[128];
    int tid = threadIdx.x;
    int t   = tid & 127;       // dim
    int grp = tid >> 7;        // 0..3

    for (int i = tid; i < CAP_V2 * HDIM; i += 512) sa[i] = 0.f;
    __syncthreads();

    int cnt2 = g_cntEB2; if (cnt2 > CAP_EB2) cnt2 = CAP_EB2;
    for (int j = grp; j < cnt2; j += 4) {
        int2 e = g_EB2[j];
        float w = g_dinv[e.y];
        atomicAdd(&sa[e.x * HDIM + t], w * g_h2s[(size_t)g_slotH2[e.y] * HDIM + t]);
    }
    __syncthreads();

    int cv2 = g_cntV2; if (cv2 > CAP_V2) cv2 = CAP_V2;
    for (int s = grp; s < cv2; s += 4) {
        int   v  = g_LV2[s];
        float di = g_dinv[v];
        float self = g_h2s[(size_t)g_slotH2[v] * HDIM + t];
        float a2 = fmaf(fmaf(self, di, sa[s * HDIM + t]), di, b2[t]);
        sa[s * HDIM + t] = fmaxf(a2, 0.f);
    }
    __syncthreads();

    if (tid < 128) {
        int cev = g_cntEV2;
        int lim = cev > CAP_EV2 ? CAP_EV2 : cev;
        float nsum = 0.f;
        for (int j = 0; j < lim; j++) {
            int s = g_EV2[j];
            nsum += sa[g_slotV2[s] * HDIM + t];
        }
        float cntf = fmaxf((float)cev, 1.f);
        sred[t] = sa[t] * fcw[t] + (nsum / cntf) * fcw[HDIM + t];
    }
    __syncthreads();
    if (tid == 0) {
        float v = fcb[0];
        for (int j = 0; j < 128; j++) v += sred[j];
        out[0] = v;
    }
}

// ---------------- launcher ---------------------------------------------------------
extern "C" void kernel_launch(void* const* d_in, const int* in_sizes, int n_in,
                              void* d_out, int out_size) {
    const float* x   = nullptr;
    const void*  ei  = nullptr;
    const float* w1  = nullptr;
    const float* b1  = nullptr;
    const float* w2  = nullptr;
    const float* b2  = nullptr;
    const float* fcw = nullptr;
    const float* fcb = nullptr;
    for (int i = 0; i < n_in; i++) {
        switch (in_sizes[i]) {
            case 12800000: x   = (const float*)d_in[i];     break;
            case 3200000:  ei  = d_in[i];                   break;
            case 100000:   break;
            case 16384:    if (!w1) w1 = (const float*)d_in[i];
                           else      w2 = (const float*)d_in[i]; break;
            case 128:      if (!b1) b1 = (const float*)d_in[i];
                           else      b2 = (const float*)d_in[i]; break;
            case 256:      fcw = (const float*)d_in[i];     break;
            case 1:        fcb = (const float*)d_in[i];     break;
            default: break;
        }
    }
    float* out = (float*)d_out;

    // device addresses of scratch symbols
    float *p_h1s = nullptr, *p_a1s = nullptr, *p_h2s = nullptr;
    int *p_LH1 = nullptr, *p_cntH1 = nullptr, *p_cntH2 = nullptr;
    __nv_bfloat16 *p_w1hi = nullptr, *p_w1lo = nullptr, *p_w2hi = nullptr, *p_w2lo = nullptr;
    cudaGetSymbolAddress((void**)&p_h1s,  g_h1s);
    cudaGetSymbolAddress((void**)&p_a1s,  g_a1s);
    cudaGetSymbolAddress((void**)&p_h2s,  g_h2s);
    cudaGetSymbolAddress((void**)&p_LH1,  g_LH1);
    cudaGetSymbolAddress((void**)&p_cntH1, g_cntH1);
    cudaGetSymbolAddress((void**)&p_cntH2, g_cntH2);
    cudaGetSymbolAddress((void**)&p_w1hi, g_w1hi);
    cudaGetSymbolAddress((void**)&p_w1lo, g_w1lo);
    cudaGetSymbolAddress((void**)&p_w2hi, g_w2hi);
    cudaGetSymbolAddress((void**)&p_w2lo, g_w2lo);

    cudaFuncSetAttribute(k_gemm_s<true>,  cudaFuncAttributeMaxDynamicSharedMemorySize, SM_TOT);
    cudaFuncSetAttribute(k_gemm_s<false>, cudaFuncAttributeMaxDynamicSharedMemorySize, SM_TOT);

    const int TB = 256;
    const int gE = (E_EDGES + TB - 1) / TB;

    k_init<<<512, 1024>>>((const long long*)ei);
    k_prep<<<gE, TB>>>(ei);
    k_dw  <<<98 + 32, 1024>>>(w1, w2);
    k_f1  <<<gE, TB>>>(ei);
    k_f2  <<<gE, TB>>>(ei);

    // sparse layer 1: h1 at H1 nodes (gathered rows of x)
    k_gemm_s<true><<<CAP_H1 / 128, TB, SM_TOT>>>(x, p_LH1, p_cntH1, CAP_H1,
                                                 p_w1hi, p_w1lo, p_h1s);
    k_agg1 <<<256, TB>>>();
    k_a1fin<<<32, TB>>>(b1);

    // sparse layer 2: h2 at H2 nodes (compact a1s rows)
    k_gemm_s<false><<<CAP_H2 / 128, TB, SM_TOT>>>(p_a1s, nullptr, p_cntH2, CAP_H2,
                                                  p_w2hi, p_w2lo, p_h2s);

    // agg2 at V2 + readout
    k_final<<<1, 512>>>(b2, fcw, fcb, out);
}